// round 2
// baseline (speedup 1.0000x reference)
#include <cuda_runtime.h>
#include <math.h>

// Problem constants
#define B_  1024
#define T_  256
#define I_  153
#define H_  128
#define G_  384           // 3*H
#define BT_ (B_ * T_)

// ---------------------------------------------------------------------------
// Scratch (static device globals; no runtime allocation allowed)
// ---------------------------------------------------------------------------
__device__ float g_gi[(size_t)BT_ * G_];    // gate input projections (reused for both layers)
__device__ float g_seq[(size_t)BT_ * H_];   // layer-0 output sequence
__device__ float g_hlast[B_ * H_];          // layer-1 final hidden state

typedef unsigned long long u64;

// ---------------------------------------------------------------------------
// Packed f32x2 helpers (Blackwell sm_103a): 2 fp32 FMAs per instruction
// ---------------------------------------------------------------------------
__device__ __forceinline__ u64 pack2(float lo, float hi) {
    u64 r;
    asm("mov.b64 %0, {%1, %2};" : "=l"(r) : "f"(lo), "f"(hi));
    return r;
}
__device__ __forceinline__ void unpack2(u64 v, float& lo, float& hi) {
    asm("mov.b64 {%0, %1}, %2;" : "=f"(lo), "=f"(hi) : "l"(v));
}
__device__ __forceinline__ u64 ffma2(u64 a, u64 b, u64 c) {
    u64 d;
    asm("fma.rn.f32x2 %0, %1, %2, %3;" : "=l"(d) : "l"(a), "l"(b), "l"(c));
    return d;
}

__device__ __forceinline__ float sigmoidf_fast(float x) {
    return 1.0f / (1.0f + __expf(-x));
}

// ---------------------------------------------------------------------------
// GEMM with bias: C[M,N] = A[M,K] @ W[N,K]^T + bias[N]
// 128x128 tile, BK=8, 256 threads, 8x8 microtile via FFMA2 (pairs over N)
// M % 128 == 0, N % 128 == 0 (M=262144, N=384). K arbitrary (153 or 128).
// ---------------------------------------------------------------------------
__global__ __launch_bounds__(256)
void sgemm_bias_kernel(const float* __restrict__ A,
                       const float* __restrict__ W,
                       const float* __restrict__ bias,
                       float* __restrict__ C,
                       int M, int N, int K) {
    __shared__ float As[8][128];
    __shared__ float Bs[8][128];

    const int bm = blockIdx.x * 128;
    const int bn = blockIdx.y * 128;
    const int tid = threadIdx.x;
    const int tx = tid & 15;       // 0..15 -> 8 columns each
    const int ty = tid >> 4;       // 0..15 -> 8 rows each

    u64 acc2[8][4] = {};           // 8 rows x 4 f32x2 pairs (=8 cols)

    for (int k0 = 0; k0 < K; k0 += 8) {
        // Load A tile: 128 rows x 8 k (zero-pad K remainder)
        #pragma unroll
        for (int i = 0; i < 4; i++) {
            int idx = tid + i * 256;        // 0..1023
            int m = idx >> 3;
            int k = idx & 7;
            float v = 0.0f;
            if (k0 + k < K) v = A[(size_t)(bm + m) * K + k0 + k];
            As[k][m] = v;
        }
        // Load W tile
        #pragma unroll
        for (int i = 0; i < 4; i++) {
            int idx = tid + i * 256;
            int n = idx >> 3;
            int k = idx & 7;
            float v = 0.0f;
            if (k0 + k < K) v = W[(size_t)(bn + n) * K + k0 + k];
            Bs[k][n] = v;
        }
        __syncthreads();

        #pragma unroll
        for (int k = 0; k < 8; k++) {
            float4 aLo = *reinterpret_cast<const float4*>(&As[k][ty * 8]);
            float4 aHi = *reinterpret_cast<const float4*>(&As[k][ty * 8 + 4]);
            float a[8] = {aLo.x, aLo.y, aLo.z, aLo.w, aHi.x, aHi.y, aHi.z, aHi.w};
            ulonglong2 b01 = *reinterpret_cast<const ulonglong2*>(&Bs[k][tx * 8]);
            ulonglong2 b23 = *reinterpret_cast<const ulonglong2*>(&Bs[k][tx * 8 + 4]);
            u64 bb[4] = {b01.x, b01.y, b23.x, b23.y};
            #pragma unroll
            for (int i = 0; i < 8; i++) {
                u64 ai = pack2(a[i], a[i]);
                #pragma unroll
                for (int jj = 0; jj < 4; jj++)
                    acc2[i][jj] = ffma2(ai, bb[jj], acc2[i][jj]);
            }
        }
        __syncthreads();
    }

    // Store with bias
    #pragma unroll
    for (int i = 0; i < 8; i++) {
        int m = bm + ty * 8 + i;
        size_t row = (size_t)m * N + bn + tx * 8;
        #pragma unroll
        for (int jj = 0; jj < 4; jj++) {
            float c0, c1;
            unpack2(acc2[i][jj], c0, c1);
            int n = bn + tx * 8 + jj * 2;
            C[row + jj * 2]     = c0 + bias[n];
            C[row + jj * 2 + 1] = c1 + bias[n + 1];
        }
    }
}

// ---------------------------------------------------------------------------
// GRU recurrent scan. One CTA = 8 batch rows, all 256 timesteps.
// W_hh (transposed, [k][g]) resident in SMEM: 128*384*4 = 192KB.
// h resident in SMEM as [k][b] (8 floats per k, 16B-aligned pairs for f32x2).
// gi (input projections incl. b_ih) streamed from global.
// 256 threads: thread = (j in 0..127, bh in {0,1} handling 4 batch rows).
// ---------------------------------------------------------------------------
#define SCAN_SMEM ((H_ * G_ + H_ * 8) * 4)

__global__ __launch_bounds__(256, 1)
void gru_scan_kernel(const float* __restrict__ gi,     // [B, T, 384]
                     const float* __restrict__ W_hh,   // [384, 128]
                     const float* __restrict__ b_hh,   // [384]
                     float* __restrict__ seq_out,      // [B, T, 128] or null
                     float* __restrict__ h_out) {      // [B, 128] or null
    extern __shared__ float sm[];
    float* Wsh = sm;                // [128][384]: Wsh[k*384 + g]
    float* hsh = sm + H_ * G_;      // [128][8]:   hsh[k*8 + b]

    const int tid = threadIdx.x;
    const int j   = tid & 127;
    const int bh4 = (tid >> 7) * 4;       // 0 or 4
    const int b0  = blockIdx.x * 8;

    // Load W_hh transposed: Wsh[k*384+g] = W_hh[g*128+k] (conflict-free STS)
    for (int idx = tid; idx < H_ * G_; idx += 256) {
        int k = idx / G_;
        int g = idx - k * G_;
        Wsh[idx] = W_hh[g * H_ + k];
    }
    for (int idx = tid; idx < H_ * 8; idx += 256) hsh[idx] = 0.0f;

    const float br  = b_hh[j];
    const float bz  = b_hh[H_ + j];
    const float bnn = b_hh[2 * H_ + j];
    __syncthreads();

    const float* wp = Wsh + j;

    for (int t = 0; t < T_; t++) {
        // Prefetch this step's gate inputs (coalesced over j)
        float ir[4], iz[4], inn[4];
        #pragma unroll
        for (int q = 0; q < 4; q++) {
            const float* gp = gi + ((size_t)(b0 + bh4 + q) * T_ + t) * G_;
            ir[q]  = gp[j];
            iz[q]  = gp[H_ + j];
            inn[q] = gp[2 * H_ + j];
        }

        // gh = h @ W_hh^T for 3 gates x 4 batch rows, via packed f32x2 FMAs
        u64 ar2[2] = {0, 0}, az2[2] = {0, 0}, an2[2] = {0, 0};
        #pragma unroll 8
        for (int k = 0; k < H_; k++) {
            ulonglong2 hv = *reinterpret_cast<const ulonglong2*>(hsh + k * 8 + bh4);
            float wr = wp[k * G_];
            float wz = wp[k * G_ + H_];
            float wn = wp[k * G_ + 2 * H_];
            u64 wr2 = pack2(wr, wr);
            u64 wz2 = pack2(wz, wz);
            u64 wn2 = pack2(wn, wn);
            ar2[0] = ffma2(wr2, hv.x, ar2[0]);
            ar2[1] = ffma2(wr2, hv.y, ar2[1]);
            az2[0] = ffma2(wz2, hv.x, az2[0]);
            az2[1] = ffma2(wz2, hv.y, az2[1]);
            an2[0] = ffma2(wn2, hv.x, an2[0]);
            an2[1] = ffma2(wn2, hv.y, an2[1]);
        }
        float ar[4], az[4], an[4];
        unpack2(ar2[0], ar[0], ar[1]); unpack2(ar2[1], ar[2], ar[3]);
        unpack2(az2[0], az[0], az[1]); unpack2(az2[1], az[2], az[3]);
        unpack2(an2[0], an[0], an[1]); unpack2(an2[1], an[2], an[3]);

        float hold[4];
        #pragma unroll
        for (int q = 0; q < 4; q++) hold[q] = hsh[j * 8 + bh4 + q];

        float hnew[4];
        #pragma unroll
        for (int q = 0; q < 4; q++) {
            float r = sigmoidf_fast(ir[q] + ar[q] + br);
            float z = sigmoidf_fast(iz[q] + az[q] + bz);
            float n = tanhf(inn[q] + r * (an[q] + bnn));
            hnew[q] = (1.0f - z) * n + z * hold[q];
        }

        __syncthreads();   // all reads of old h done
        *reinterpret_cast<float4*>(hsh + j * 8 + bh4) =
            make_float4(hnew[0], hnew[1], hnew[2], hnew[3]);
        if (seq_out) {
            #pragma unroll
            for (int q = 0; q < 4; q++)
                seq_out[((size_t)(b0 + bh4 + q) * T_ + t) * H_ + j] = hnew[q];
        }
        __syncthreads();   // new h visible
    }

    if (h_out) {
        #pragma unroll
        for (int q = 0; q < 4; q++)
            h_out[(b0 + bh4 + q) * H_ + j] = hsh[j * 8 + bh4 + q];
    }
}

// ---------------------------------------------------------------------------
// Head: out[b] = sigmoid(W2 @ relu(W1 @ h[b] + b1) + b2)
// One block (64 threads) per batch row.
// ---------------------------------------------------------------------------
__global__ __launch_bounds__(64)
void head_kernel(const float* __restrict__ h,
                 const float* __restrict__ W1, const float* __restrict__ b1,
                 const float* __restrict__ W2, const float* __restrict__ b2,
                 float* __restrict__ out) {
    __shared__ float hs[128];
    __shared__ float red[2];
    const int b = blockIdx.x;
    const int tid = threadIdx.x;   // 0..63

    hs[tid]      = h[b * 128 + tid];
    hs[tid + 64] = h[b * 128 + 64 + tid];
    __syncthreads();

    float acc = b1[tid];
    #pragma unroll 8
    for (int k = 0; k < 128; k++) acc += W1[tid * 128 + k] * hs[k];
    float v = fmaxf(acc, 0.0f) * W2[tid];

    #pragma unroll
    for (int o = 16; o > 0; o >>= 1) v += __shfl_down_sync(0xffffffffu, v, o);
    if ((tid & 31) == 0) red[tid >> 5] = v;
    __syncthreads();
    if (tid == 0) {
        float s = red[0] + red[1] + b2[0];
        out[b] = 1.0f / (1.0f + expf(-s));
    }
}

// ---------------------------------------------------------------------------
// Launch
// ---------------------------------------------------------------------------
extern "C" void kernel_launch(void* const* d_in, const int* in_sizes, int n_in,
                              void* d_out, int out_size) {
    const float* x     = (const float*)d_in[0];
    const float* W_ih0 = (const float*)d_in[1];
    const float* W_hh0 = (const float*)d_in[2];
    const float* b_ih0 = (const float*)d_in[3];
    const float* b_hh0 = (const float*)d_in[4];
    const float* W_ih1 = (const float*)d_in[5];
    const float* W_hh1 = (const float*)d_in[6];
    const float* b_ih1 = (const float*)d_in[7];
    const float* b_hh1 = (const float*)d_in[8];
    const float* W1    = (const float*)d_in[9];
    const float* b1    = (const float*)d_in[10];
    const float* W2    = (const float*)d_in[11];
    const float* b2    = (const float*)d_in[12];
    float* out = (float*)d_out;

    void *gi_p, *seq_p, *hl_p;
    cudaGetSymbolAddress(&gi_p, g_gi);
    cudaGetSymbolAddress(&seq_p, g_seq);
    cudaGetSymbolAddress(&hl_p, g_hlast);
    float* gi    = (float*)gi_p;
    float* seq   = (float*)seq_p;
    float* hlast = (float*)hl_p;

    cudaFuncSetAttribute((const void*)gru_scan_kernel,
                         cudaFuncAttributeMaxDynamicSharedMemorySize, SCAN_SMEM);

    dim3 gemm_grid(BT_ / 128, G_ / 128);

    // Layer 0: input projection, then recurrent scan (produces full sequence)
    sgemm_bias_kernel<<<gemm_grid, 256>>>(x, W_ih0, b_ih0, gi, BT_, G_, I_);
    gru_scan_kernel<<<B_ / 8, 256, SCAN_SMEM>>>(gi, W_hh0, b_hh0, seq, nullptr);

    // Layer 1: input projection on layer-0 sequence, then scan (last hidden only)
    sgemm_bias_kernel<<<gemm_grid, 256>>>(seq, W_ih1, b_ih1, gi, BT_, G_, H_);
    gru_scan_kernel<<<B_ / 8, 256, SCAN_SMEM>>>(gi, W_hh1, b_hh1, nullptr, hlast);

    // Head
    head_kernel<<<B_, 64>>>(hlast, W1, b1, W2, b2, out);
}